// round 3
// baseline (speedup 1.0000x reference)
#include <cuda_runtime.h>
#include <cuda_fp16.h>
#include <cstdint>

#define B_  32
#define T_  128
#define H_  512
#define V_  32000
#define G_  2048      // 4*H
#define M4_ 4096      // B*T

// ---------------- device scratch (no allocs allowed) ----------------
__device__ __align__(16) __half  g_Eh[V_ * H_];          // fp16 E (32.8 MB)
__device__ __align__(16) __half  g_Wih_h[G_ * H_];       // fp16 W_ih
__device__ __align__(16) float   g_biasc[G_];            // b_ih + b_hh
__device__ __align__(16) __half  g_Xe[M4_ * H_];         // gathered embeddings
__device__ __align__(16) float   g_Xg[(size_t)M4_ * G_]; // input-side gates (33.6 MB)
__device__ __align__(16) __half  g_Hall[M4_ * H_];       // all hidden states fp16
__device__ __align__(16) float   g_hbuf[2 * B_ * H_];    // double-buffered h
__device__ __align__(16) int     g_tok[M4_];             // decoded teacher-forced tokens
__device__ unsigned g_bar;

// ---------------- token decode with dtype sniffing ----------------
// Reference declares int64 but JAX default x64-disabled materializes int32.
// View as int32: int64 little-endian => odd words (high halves) all zero.
__global__ void tok_kernel(const int* __restrict__ t32)
{
    int acc = 0;
    #pragma unroll
    for (int j = 1; j < 128; j += 2) acc |= t32[j];
    bool is64 = (acc == 0);

    int m = blockIdx.x * blockDim.x + threadIdx.x;
    if (m < M4_) {
        int t = m >> 5, b = m & 31;   // row m = t*32 + b
        int tok = 1;                   // START_IDX
        if (t > 0) {
            int idx = b * T_ + t - 1;
            tok = is64 ? t32[2 * idx] : t32[idx];
        }
        if (tok < 0) tok = 0;
        if (tok >= V_) tok = V_ - 1;
        g_tok[m] = tok;
    }
}

// ---------------- prep ----------------
__global__ void prep_kernel(const float* __restrict__ enc,
                            const float* __restrict__ E,
                            const float* __restrict__ W_ih,
                            const float* __restrict__ b_ih,
                            const float* __restrict__ b_hh)
{
    long long stride = (long long)gridDim.x * blockDim.x;
    long long tid0 = (long long)blockIdx.x * blockDim.x + threadIdx.x;

    for (long long i = tid0; i < (long long)V_ * H_; i += stride)
        g_Eh[i] = __float2half(E[i]);
    for (long long i = tid0; i < (long long)G_ * H_; i += stride)
        g_Wih_h[i] = __float2half(W_ih[i]);
    for (long long i = tid0; i < G_; i += stride)
        g_biasc[i] = b_ih[i] + b_hh[i];
    for (long long i = tid0; i < (long long)M4_ * H_; i += stride) {
        int m = (int)(i >> 9), k = (int)(i & 511);
        int tok = g_tok[m];
        g_Xe[i] = __float2half(E[(long long)tok * H_ + k]);
    }
    for (long long i = tid0; i < B_ * H_; i += stride)
        g_hbuf[i] = enc[i];
    if (tid0 == 0) g_bar = 0u;
}

// ---------------- fp16 mma GEMM: C = A @ B^T (+bias), A[m][k], B[n][k] ----------------
__device__ __forceinline__ uint32_t cvta_s(const void* p) {
    return (uint32_t)__cvta_generic_to_shared(p);
}
__device__ __forceinline__ void cp16(uint32_t d, const void* s) {
    asm volatile("cp.async.cg.shared.global [%0], [%1], 16;" :: "r"(d), "l"(s));
}
__device__ __forceinline__ void ldm4(uint32_t& r0, uint32_t& r1, uint32_t& r2, uint32_t& r3, uint32_t a) {
    asm volatile("ldmatrix.sync.aligned.m8n8.x4.shared.b16 {%0,%1,%2,%3},[%4];"
                 : "=r"(r0), "=r"(r1), "=r"(r2), "=r"(r3) : "r"(a));
}
__device__ __forceinline__ void mma16816(float* c, const uint32_t* a, const uint32_t* b) {
    asm volatile("mma.sync.aligned.m16n8k16.row.col.f32.f16.f16.f32 "
                 "{%0,%1,%2,%3},{%4,%5,%6,%7},{%8,%9},{%0,%1,%2,%3};"
                 : "+f"(c[0]), "+f"(c[1]), "+f"(c[2]), "+f"(c[3])
                 : "r"(a[0]), "r"(a[1]), "r"(a[2]), "r"(a[3]), "r"(b[0]), "r"(b[1]));
}

#define SPAD 40  // halfs per smem row (32 data + 8 pad)

__global__ __launch_bounds__(256, 2)
void hgemm_kernel(const float* __restrict__ bias_ext,
                  float* __restrict__ out_ext, int N, int mode)
{
    const __half* A    = mode ? g_Hall : g_Xe;
    const __half* Bm   = mode ? g_Eh   : g_Wih_h;
    const float*  bias = mode ? bias_ext : g_biasc;
    float*        C    = mode ? out_ext : g_Xg;
    const int K = H_;
    const int m0 = blockIdx.y * 128, n0 = blockIdx.x * 128;

    __shared__ __align__(16) __half As[2][128 * SPAD];
    __shared__ __align__(16) __half Bs[2][128 * SPAD];

    int tid = threadIdx.x, lane = tid & 31, warp = tid >> 5;
    int wm = warp >> 2, wn = warp & 3;   // 2x4 warps, warp tile 64m x 32n

    float acc[4][4][4];
    #pragma unroll
    for (int i = 0; i < 4; i++)
        #pragma unroll
        for (int j = 0; j < 4; j++)
            #pragma unroll
            for (int v = 0; v < 4; v++) acc[i][j][v] = 0.f;

    const __half* gA = A  + (size_t)m0 * K;
    const __half* gB = Bm + (size_t)n0 * K;

    auto load_stage = [&](int s, int ko) {
        #pragma unroll
        for (int id = tid; id < 512; id += 256) {
            int r = id >> 2, c = id & 3;
            cp16(cvta_s(&As[s][r * SPAD + c * 8]), gA + (size_t)r * K + ko + c * 8);
            cp16(cvta_s(&Bs[s][r * SPAD + c * 8]), gB + (size_t)r * K + ko + c * 8);
        }
        asm volatile("cp.async.commit_group;");
    };

    load_stage(0, 0);
    #pragma unroll 1
    for (int it = 0; it < 16; ++it) {           // K=512 / 32
        if (it < 15) load_stage((it + 1) & 1, (it + 1) * 32);
        else asm volatile("cp.async.commit_group;");
        asm volatile("cp.async.wait_group 1;");
        __syncthreads();
        int s = it & 1;
        #pragma unroll
        for (int kk = 0; kk < 32; kk += 16) {
            uint32_t af[4][4], bf[4][2];
            int rsel = lane & 15;
            int csel = kk + ((lane >> 4) << 3);
            #pragma unroll
            for (int mi = 0; mi < 4; mi++) {
                uint32_t a = cvta_s(&As[s][(wm * 64 + mi * 16 + rsel) * SPAD + csel]);
                ldm4(af[mi][0], af[mi][1], af[mi][2], af[mi][3], a);
            }
            #pragma unroll
            for (int p = 0; p < 2; p++) {
                uint32_t r0, r1, r2, r3;
                uint32_t a = cvta_s(&Bs[s][(wn * 32 + p * 16 + rsel) * SPAD + csel]);
                ldm4(r0, r1, r2, r3, a);
                bf[2 * p][0] = r0;     bf[2 * p][1] = r2;
                bf[2 * p + 1][0] = r1; bf[2 * p + 1][1] = r3;
            }
            #pragma unroll
            for (int mi = 0; mi < 4; mi++)
                #pragma unroll
                for (int nj = 0; nj < 4; nj++)
                    mma16816(acc[mi][nj], af[mi], bf[nj]);
        }
        __syncthreads();
    }

    int g = lane >> 2, t4 = lane & 3;
    #pragma unroll
    for (int mi = 0; mi < 4; mi++) {
        #pragma unroll
        for (int nj = 0; nj < 4; nj++) {
            int mr = m0 + wm * 64 + mi * 16 + g;
            int nc = n0 + wn * 32 + nj * 8 + t4 * 2;
            float b0v = bias[nc], b1v = bias[nc + 1];
            if (mode == 0) {
                C[(size_t)mr * N + nc]           = acc[mi][nj][0] + b0v;
                C[(size_t)mr * N + nc + 1]       = acc[mi][nj][1] + b1v;
                C[(size_t)(mr + 8) * N + nc]     = acc[mi][nj][2] + b0v;
                C[(size_t)(mr + 8) * N + nc + 1] = acc[mi][nj][3] + b1v;
            } else {
                int t1 = mr >> 5, b1 = mr & 31;
                int m2 = mr + 8, t2 = m2 >> 5, b2 = m2 & 31;
                C[((size_t)b1 * T_ + t1) * V_ + nc]     = acc[mi][nj][0] + b0v;
                C[((size_t)b1 * T_ + t1) * V_ + nc + 1] = acc[mi][nj][1] + b1v;
                C[((size_t)b2 * T_ + t2) * V_ + nc]     = acc[mi][nj][2] + b0v;
                C[((size_t)b2 * T_ + t2) * V_ + nc + 1] = acc[mi][nj][3] + b1v;
            }
        }
    }
}

// ---------------- persistent LSTM recurrence ----------------
// 128 CTAs x 256 thr. CTA cb owns hidden units cb*4..cb*4+3 (16 gate rows).
// Warp w computes local rows 2w,2w+1 (lane = batch). Warps 0..3 do the
// elementwise update for unit w; c-state lives in registers.
__global__ void lstm_rec_kernel(const float* __restrict__ W_hh,
                                const float* __restrict__ enc)
{
    extern __shared__ __align__(16) float sm[];
    float* Ws = sm;                 // 16 x 512
    float* hs = Ws + 16 * 512;      // 32 x 516
    float* gs = hs + 32 * 516;      // 16 x 33

    const int cb = blockIdx.x;
    const int tid = threadIdx.x, lane = tid & 31, w = tid >> 5;
    const unsigned nb = gridDim.x;

    for (int i = tid; i < 16 * 512; i += 256) {
        int r = i >> 9, k = i & 511;
        int q = r >> 2, iu = r & 3;
        Ws[i] = W_hh[(size_t)((q << 9) + (cb << 2) + iu) * H_ + k];
    }
    float cst = 0.f;
    if (w < 4) cst = enc[lane * H_ + (cb << 2) + w];   // c0

    const int r0 = 2 * w, r1 = 2 * w + 1;
    const float* Wr0 = Ws + (r0 << 9);
    const float* Wr1 = Ws + (r1 << 9);
    const int gcol0 = ((r0 >> 2) << 9) + (cb << 2) + (r0 & 3);
    const int gcol1 = ((r1 >> 2) << 9) + (cb << 2) + (r1 & 3);
    __syncthreads();

    for (int t = 0; t < T_; t++) {
        const float* hin = g_hbuf + (t & 1) * (B_ * H_);
        for (int i = tid; i < B_ * (H_ / 4); i += 256) {
            int b = i >> 7, k4 = i & 127;
            float4 v = __ldcg((const float4*)(hin + b * H_ + (k4 << 2)));
            *(float4*)(hs + b * 516 + (k4 << 2)) = v;
        }
        __syncthreads();

        float s00 = 0, s01 = 0, s02 = 0, s03 = 0, s10 = 0, s11 = 0, s12 = 0, s13 = 0;
        const float* hrow = hs + lane * 516;
        #pragma unroll 8
        for (int k = 0; k < 512; k += 4) {
            float4 h4 = *(const float4*)(hrow + k);
            float4 w0 = *(const float4*)(Wr0 + k);
            float4 w1 = *(const float4*)(Wr1 + k);
            s00 += h4.x * w0.x; s01 += h4.y * w0.y; s02 += h4.z * w0.z; s03 += h4.w * w0.w;
            s10 += h4.x * w1.x; s11 += h4.y * w1.y; s12 += h4.z * w1.z; s13 += h4.w * w1.w;
        }
        const float* xg = g_Xg + (size_t)(t * B_ + lane) * G_;
        gs[r0 * 33 + lane] = xg[gcol0] + (s00 + s01) + (s02 + s03);
        gs[r1 * 33 + lane] = xg[gcol1] + (s10 + s11) + (s12 + s13);
        __syncthreads();

        if (w < 4) {
            float gi = gs[(0 * 4 + w) * 33 + lane];
            float gf = gs[(1 * 4 + w) * 33 + lane];
            float gg = gs[(2 * 4 + w) * 33 + lane];
            float go = gs[(3 * 4 + w) * 33 + lane];
            float i_ = 1.f / (1.f + __expf(-gi));
            float f_ = 1.f / (1.f + __expf(-gf));
            float gv = tanhf(gg);
            float o_ = 1.f / (1.f + __expf(-go));
            cst = f_ * cst + i_ * gv;
            float hv = o_ * tanhf(cst);
            g_hbuf[((t + 1) & 1) * (B_ * H_) + lane * H_ + (cb << 2) + w] = hv;
            g_Hall[(size_t)(t * B_ + lane) * H_ + (cb << 2) + w] = __float2half(hv);
        }
        __threadfence();
        __syncthreads();
        if (tid == 0) {
            atomicAdd(&g_bar, 1u);
            unsigned tgt = (unsigned)(t + 1) * nb;
            volatile unsigned* vb = &g_bar;
            while (*vb < tgt) { }
        }
        __syncthreads();
    }
}

// ---------------- launch ----------------
extern "C" void kernel_launch(void* const* d_in, const int* in_sizes, int n_in,
                              void* d_out, int out_size)
{
    const float* enc   = (const float*)d_in[0];
    const int*   tgt32 = (const int*)d_in[1];   // int32 or int64 viewed as int32; sniffed on device
    const float* E     = (const float*)d_in[2];
    const float* W_ih  = (const float*)d_in[3];
    const float* W_hh  = (const float*)d_in[4];
    const float* b_ih  = (const float*)d_in[5];
    const float* b_hh  = (const float*)d_in[6];
    const float* b_out = (const float*)d_in[7];
    float* out = (float*)d_out;

    tok_kernel<<<M4_ / 256, 256>>>(tgt32);
    prep_kernel<<<4096, 256>>>(enc, E, W_ih, b_ih, b_hh);

    dim3 g0(G_ / 128, M4_ / 128);                  // (16, 32)
    hgemm_kernel<<<g0, 256>>>(b_out, out, G_, 0);

    int lstm_smem = (16 * 512 + 32 * 516 + 16 * 33) * (int)sizeof(float);
    cudaFuncSetAttribute(lstm_rec_kernel,
                         cudaFuncAttributeMaxDynamicSharedMemorySize, lstm_smem);
    lstm_rec_kernel<<<128, 256, lstm_smem>>>(W_hh, enc);

    dim3 g1(V_ / 128, M4_ / 128);                  // (250, 32)
    hgemm_kernel<<<g1, 256>>>(b_out, out, V_, 1);
}

// round 5
// speedup vs baseline: 1.0266x; 1.0266x over previous
#include <cuda_runtime.h>
#include <cuda_fp16.h>
#include <cstdint>

#define B_  32
#define T_  128
#define H_  512
#define V_  32000
#define G_  2048      // 4*H
#define M4_ 4096      // B*T

// ---------------- device scratch ----------------
__device__ __align__(16) __half  g_Eh[V_ * H_];
__device__ __align__(16) __half  g_Wih_h[G_ * H_];
__device__ __align__(16) float   g_biasc[G_];
__device__ __align__(16) __half  g_Xe[M4_ * H_];
__device__ __align__(16) float   g_Xg[(size_t)M4_ * G_];
__device__ __align__(16) __half  g_Hall[M4_ * H_];
__device__ __align__(16) __half  g_h0h[B_ * H_];     // h0 in fp16
__device__ __align__(16) int     g_tok[M4_];
__device__ unsigned g_bar;

// ---------------- token decode (dtype sniffing) ----------------
__global__ void tok_kernel(const int* __restrict__ t32)
{
    int acc = 0;
    #pragma unroll
    for (int j = 1; j < 128; j += 2) acc |= t32[j];
    bool is64 = (acc == 0);

    int m = blockIdx.x * blockDim.x + threadIdx.x;
    if (m < M4_) {
        int t = m >> 5, b = m & 31;
        int tok = 1;
        if (t > 0) {
            int idx = b * T_ + t - 1;
            tok = is64 ? t32[2 * idx] : t32[idx];
        }
        if (tok < 0) tok = 0;
        if (tok >= V_) tok = V_ - 1;
        g_tok[m] = tok;
    }
}

// ---------------- prep ----------------
__global__ void prep_kernel(const float* __restrict__ enc,
                            const float* __restrict__ E,
                            const float* __restrict__ W_ih,
                            const float* __restrict__ b_ih,
                            const float* __restrict__ b_hh)
{
    long long stride = (long long)gridDim.x * blockDim.x;
    long long tid0 = (long long)blockIdx.x * blockDim.x + threadIdx.x;

    for (long long i = tid0; i < (long long)V_ * H_; i += stride)
        g_Eh[i] = __float2half(E[i]);
    for (long long i = tid0; i < (long long)G_ * H_; i += stride)
        g_Wih_h[i] = __float2half(W_ih[i]);
    for (long long i = tid0; i < G_; i += stride)
        g_biasc[i] = b_ih[i] + b_hh[i];
    for (long long i = tid0; i < (long long)M4_ * H_; i += stride) {
        int m = (int)(i >> 9), k = (int)(i & 511);
        int tok = g_tok[m];
        g_Xe[i] = __float2half(E[(long long)tok * H_ + k]);
    }
    for (long long i = tid0; i < B_ * H_; i += stride)
        g_h0h[i] = __float2half(enc[i]);
    if (tid0 == 0) g_bar = 0u;
}

// ---------------- common PTX helpers ----------------
__device__ __forceinline__ uint32_t cvta_s(const void* p) {
    return (uint32_t)__cvta_generic_to_shared(p);
}
__device__ __forceinline__ void cp16(uint32_t d, const void* s) {
    asm volatile("cp.async.cg.shared.global [%0], [%1], 16;" :: "r"(d), "l"(s));
}
__device__ __forceinline__ void ldm4(uint32_t& r0, uint32_t& r1, uint32_t& r2, uint32_t& r3, uint32_t a) {
    asm volatile("ldmatrix.sync.aligned.m8n8.x4.shared.b16 {%0,%1,%2,%3},[%4];"
                 : "=r"(r0), "=r"(r1), "=r"(r2), "=r"(r3) : "r"(a));
}
__device__ __forceinline__ void mma16816(float* c, const uint32_t* a, const uint32_t* b) {
    asm volatile("mma.sync.aligned.m16n8k16.row.col.f32.f16.f16.f32 "
                 "{%0,%1,%2,%3},{%4,%5,%6,%7},{%8,%9},{%0,%1,%2,%3};"
                 : "+f"(c[0]), "+f"(c[1]), "+f"(c[2]), "+f"(c[3])
                 : "r"(a[0]), "r"(a[1]), "r"(a[2]), "r"(a[3]), "r"(b[0]), "r"(b[1]));
}

// ---------------- hgemm (GEMM1 + GEMM2, proven in R3) ----------------
#define SPAD 40

__global__ __launch_bounds__(256, 2)
void hgemm_kernel(const float* __restrict__ bias_ext,
                  float* __restrict__ out_ext, int N, int mode)
{
    const __half* A    = mode ? g_Hall : g_Xe;
    const __half* Bm   = mode ? g_Eh   : g_Wih_h;
    const float*  bias = mode ? bias_ext : g_biasc;
    float*        C    = mode ? out_ext : g_Xg;
    const int K = H_;
    const int m0 = blockIdx.y * 128, n0 = blockIdx.x * 128;

    __shared__ __align__(16) __half As[2][128 * SPAD];
    __shared__ __align__(16) __half Bs[2][128 * SPAD];

    int tid = threadIdx.x, lane = tid & 31, warp = tid >> 5;
    int wm = warp >> 2, wn = warp & 3;

    float acc[4][4][4];
    #pragma unroll
    for (int i = 0; i < 4; i++)
        #pragma unroll
        for (int j = 0; j < 4; j++)
            #pragma unroll
            for (int v = 0; v < 4; v++) acc[i][j][v] = 0.f;

    const __half* gA = A  + (size_t)m0 * K;
    const __half* gB = Bm + (size_t)n0 * K;

    auto load_stage = [&](int s, int ko) {
        #pragma unroll
        for (int id = tid; id < 512; id += 256) {
            int r = id >> 2, c = id & 3;
            cp16(cvta_s(&As[s][r * SPAD + c * 8]), gA + (size_t)r * K + ko + c * 8);
            cp16(cvta_s(&Bs[s][r * SPAD + c * 8]), gB + (size_t)r * K + ko + c * 8);
        }
        asm volatile("cp.async.commit_group;");
    };

    load_stage(0, 0);
    #pragma unroll 1
    for (int it = 0; it < 16; ++it) {
        if (it < 15) load_stage((it + 1) & 1, (it + 1) * 32);
        else asm volatile("cp.async.commit_group;");
        asm volatile("cp.async.wait_group 1;");
        __syncthreads();
        int s = it & 1;
        #pragma unroll
        for (int kk = 0; kk < 32; kk += 16) {
            uint32_t af[4][4], bf[4][2];
            int rsel = lane & 15;
            int csel = kk + ((lane >> 4) << 3);
            #pragma unroll
            for (int mi = 0; mi < 4; mi++) {
                uint32_t a = cvta_s(&As[s][(wm * 64 + mi * 16 + rsel) * SPAD + csel]);
                ldm4(af[mi][0], af[mi][1], af[mi][2], af[mi][3], a);
            }
            #pragma unroll
            for (int p = 0; p < 2; p++) {
                uint32_t r0, r1, r2, r3;
                uint32_t a = cvta_s(&Bs[s][(wn * 32 + p * 16 + rsel) * SPAD + csel]);
                ldm4(r0, r1, r2, r3, a);
                bf[2 * p][0] = r0;     bf[2 * p][1] = r2;
                bf[2 * p + 1][0] = r1; bf[2 * p + 1][1] = r3;
            }
            #pragma unroll
            for (int mi = 0; mi < 4; mi++)
                #pragma unroll
                for (int nj = 0; nj < 4; nj++)
                    mma16816(acc[mi][nj], af[mi], bf[nj]);
        }
        __syncthreads();
    }

    int g = lane >> 2, t4 = lane & 3;
    #pragma unroll
    for (int mi = 0; mi < 4; mi++) {
        #pragma unroll
        for (int nj = 0; nj < 4; nj++) {
            int mr = m0 + wm * 64 + mi * 16 + g;
            int nc = n0 + wn * 32 + nj * 8 + t4 * 2;
            float b0v = bias[nc], b1v = bias[nc + 1];
            if (mode == 0) {
                C[(size_t)mr * N + nc]           = acc[mi][nj][0] + b0v;
                C[(size_t)mr * N + nc + 1]       = acc[mi][nj][1] + b1v;
                C[(size_t)(mr + 8) * N + nc]     = acc[mi][nj][2] + b0v;
                C[(size_t)(mr + 8) * N + nc + 1] = acc[mi][nj][3] + b1v;
            } else {
                int t1 = mr >> 5, b1 = mr & 31;
                int m2 = mr + 8, t2 = m2 >> 5, b2 = m2 & 31;
                C[((size_t)b1 * T_ + t1) * V_ + nc]     = acc[mi][nj][0] + b0v;
                C[((size_t)b1 * T_ + t1) * V_ + nc + 1] = acc[mi][nj][1] + b1v;
                C[((size_t)b2 * T_ + t2) * V_ + nc]     = acc[mi][nj][2] + b0v;
                C[((size_t)b2 * T_ + t2) * V_ + nc + 1] = acc[mi][nj][3] + b1v;
            }
        }
    }
}

// ---------------- persistent LSTM recurrence, tensor-core version ----------------
// 128 CTAs x 256 thr. CTA cb owns units cb*4..cb*4+3 -> 16 gate rows
// (local row r = q*4+iu, global W row q*512 + cb*4 + iu).
// Per step: gates[32 b][16 r] = h_fp16[32x512] @ Whh_fp16[16x512]^T via mma,
// warp w covers k in [64w, 64w+64), partials reduced in smem.
#define HS_STR 520    // halfs per h-row (512 + 8 pad; rows 1040B -> 4-bank skew)
#define WS_STR 520
#define P_STR  18

__global__ __launch_bounds__(256, 1)
void lstm_mma_kernel(const float* __restrict__ W_hh,
                     const float* __restrict__ enc)
{
    extern __shared__ __align__(16) char smraw[];
    __half* Hs = (__half*)smraw;                    // 32 x 520
    __half* Ws = Hs + 32 * HS_STR;                  // 16 x 520
    float*  P  = (float*)(Ws + 16 * WS_STR);        // 8 x 32 x 18
    float*  R  = P + 8 * 32 * P_STR;                // 32 x 18

    const int cb = blockIdx.x;
    const int tid = threadIdx.x, lane = tid & 31, w = tid >> 5;
    const unsigned nb = gridDim.x;

    // W_hh (16 rows x 512) -> smem fp16
    for (int i = tid; i < 16 * 512; i += 256) {
        int r = i >> 9, k = i & 511;
        int q = r >> 2, iu = r & 3;
        Ws[r * WS_STR + k] = __float2half(W_hh[(size_t)((q << 9) + (cb << 2) + iu) * H_ + k]);
    }
    float cst = 0.f;
    if (w < 4) cst = enc[lane * H_ + (cb << 2) + w];   // c0 fp32

    const int rsel = lane & 15;
    const int csel0 = (w << 6) + ((lane >> 4) << 3);
    const int grp = lane >> 2, t4 = lane & 3;
    __syncthreads();

    for (int t = 0; t < T_; t++) {
        // stage h_{t-1} fp16 into smem (L2 reads; writers fenced via barrier)
        const __half* hin = (t == 0) ? g_h0h : g_Hall + (size_t)(t - 1) * (B_ * H_);
        for (int i = tid; i < B_ * (H_ / 8); i += 256) {   // 2048 x 16B
            int b = i >> 6, k8 = i & 63;
            uint4 v = __ldcg((const uint4*)(hin + b * H_ + (k8 << 3)));
            *(uint4*)(Hs + b * HS_STR + (k8 << 3)) = v;
        }
        __syncthreads();

        // mma over this warp's k-chunk
        float acc[2][2][4];
        #pragma unroll
        for (int mi = 0; mi < 2; mi++)
            #pragma unroll
            for (int nj = 0; nj < 2; nj++)
                #pragma unroll
                for (int v = 0; v < 4; v++) acc[mi][nj][v] = 0.f;

        #pragma unroll
        for (int kk = 0; kk < 64; kk += 16) {
            int csel = csel0 + kk;
            uint32_t af[2][4], bf[2][2];
            #pragma unroll
            for (int mi = 0; mi < 2; mi++) {
                uint32_t a = cvta_s(&Hs[(mi * 16 + rsel) * HS_STR + csel]);
                ldm4(af[mi][0], af[mi][1], af[mi][2], af[mi][3], a);
            }
            {
                uint32_t r0, r1, r2, r3;
                uint32_t a = cvta_s(&Ws[rsel * WS_STR + csel]);
                ldm4(r0, r1, r2, r3, a);
                bf[0][0] = r0; bf[0][1] = r2;
                bf[1][0] = r1; bf[1][1] = r3;
            }
            #pragma unroll
            for (int mi = 0; mi < 2; mi++)
                #pragma unroll
                for (int nj = 0; nj < 2; nj++)
                    mma16816(acc[mi][nj], af[mi], bf[nj]);
        }

        // write partials: m = mi*16 + grp + 8*(v>>1), n = nj*8 + t4*2 + (v&1)
        float* Pw = P + w * 32 * P_STR;
        #pragma unroll
        for (int mi = 0; mi < 2; mi++)
            #pragma unroll
            for (int nj = 0; nj < 2; nj++) {
                int mbase = mi * 16 + grp, nbase = nj * 8 + t4 * 2;
                Pw[mbase * P_STR + nbase]           = acc[mi][nj][0];
                Pw[mbase * P_STR + nbase + 1]       = acc[mi][nj][1];
                Pw[(mbase + 8) * P_STR + nbase]     = acc[mi][nj][2];
                Pw[(mbase + 8) * P_STR + nbase + 1] = acc[mi][nj][3];
            }
        __syncthreads();

        // reduce 8 partials -> R[32][16]
        for (int o = tid; o < 512; o += 256) {
            int m = o >> 4, n = o & 15;
            float s = 0.f;
            #pragma unroll
            for (int ww = 0; ww < 8; ww++) s += P[(ww * 32 + m) * P_STR + n];
            R[m * P_STR + n] = s;
        }
        __syncthreads();

        // elementwise LSTM for this CTA's 4 units (b=lane, unit=w)
        if (w < 4) {
            int b = lane;
            const float* xg = g_Xg + (size_t)(t * B_ + b) * G_ + (cb << 2) + w;
            float gi = R[b * P_STR + (0 * 4 + w)] + xg[0 * 512];
            float gf = R[b * P_STR + (1 * 4 + w)] + xg[1 * 512];
            float gg = R[b * P_STR + (2 * 4 + w)] + xg[2 * 512];
            float go = R[b * P_STR + (3 * 4 + w)] + xg[3 * 512];
            float i_ = 1.f / (1.f + __expf(-gi));
            float f_ = 1.f / (1.f + __expf(-gf));
            float gv = tanhf(gg);
            float o_ = 1.f / (1.f + __expf(-go));
            cst = f_ * cst + i_ * gv;
            float hv = o_ * tanhf(cst);
            g_Hall[(size_t)(t * B_ + b) * H_ + (cb << 2) + w] = __float2half(hv);
        }
        __threadfence();
        __syncthreads();
        if (tid == 0) {
            atomicAdd(&g_bar, 1u);
            unsigned tgt = (unsigned)(t + 1) * nb;
            volatile unsigned* vb = &g_bar;
            while (*vb < tgt) { }
        }
        __syncthreads();
    }
}

// ---------------- launch ----------------
extern "C" void kernel_launch(void* const* d_in, const int* in_sizes, int n_in,
                              void* d_out, int out_size)
{
    const float* enc   = (const float*)d_in[0];
    const int*   tgt32 = (const int*)d_in[1];
    const float* E     = (const float*)d_in[2];
    const float* W_ih  = (const float*)d_in[3];
    const float* W_hh  = (const float*)d_in[4];
    const float* b_ih  = (const float*)d_in[5];
    const float* b_hh  = (const float*)d_in[6];
    const float* b_out = (const float*)d_in[7];
    float* out = (float*)d_out;

    tok_kernel<<<M4_ / 256, 256>>>(tgt32);
    prep_kernel<<<4096, 256>>>(enc, E, W_ih, b_ih, b_hh);

    dim3 g0(G_ / 128, M4_ / 128);
    hgemm_kernel<<<g0, 256>>>(b_out, out, G_, 0);

    int lstm_smem = (32 * HS_STR + 16 * WS_STR) * 2 + (8 * 32 * P_STR + 32 * P_STR) * 4;
    cudaFuncSetAttribute(lstm_mma_kernel,
                         cudaFuncAttributeMaxDynamicSharedMemorySize, lstm_smem);
    lstm_mma_kernel<<<128, 256, lstm_smem>>>(W_hh, enc);

    dim3 g1(V_ / 128, M4_ / 128);                  // (250, 32)
    hgemm_kernel<<<g1, 256>>>(b_out, out, V_, 1);
}

// round 6
// speedup vs baseline: 1.9004x; 1.8511x over previous
#include <cuda_runtime.h>
#include <cuda_fp16.h>
#include <cstdint>

#define B_  32
#define T_  128
#define H_  512
#define V_  32000
#define G_  2048      // 4*H
#define M4_ 4096      // B*T
#define NB_ 128       // recurrence CTAs
#define NTM 32        // m-tiles (M4/128)
#define NTN 250       // n-tiles (V/128)
#define TILES (NTM * NTN)

// ---------------- device scratch ----------------
__device__ __align__(16) __half  g_Eh[V_ * H_];
__device__ __align__(16) __half  g_Wih_h[G_ * H_];
__device__ __align__(16) float   g_biasc[G_];
__device__ __align__(16) __half  g_Xe[M4_ * H_];
__device__ __align__(16) float   g_Xg[(size_t)M4_ * G_];
__device__ __align__(16) __half  g_Hall[M4_ * H_];
__device__ __align__(16) __half  g_h0h[B_ * H_];
__device__ __align__(16) int     g_tok[M4_];
__device__ unsigned g_bar;
__device__ unsigned g_tile;

// ---------------- sync helpers ----------------
__device__ __forceinline__ void rel_add(unsigned* p) {
    asm volatile("red.release.gpu.global.add.u32 [%0], %1;" :: "l"(p), "r"(1u) : "memory");
}
__device__ __forceinline__ unsigned acq_ld(unsigned* p) {
    unsigned v;
    asm volatile("ld.acquire.gpu.global.u32 %0, [%1];" : "=r"(v) : "l"(p) : "memory");
    return v;
}

// ---------------- token decode (dtype sniffing) ----------------
__global__ void tok_kernel(const int* __restrict__ t32)
{
    int acc = 0;
    #pragma unroll
    for (int j = 1; j < 128; j += 2) acc |= t32[j];
    bool is64 = (acc == 0);

    int m = blockIdx.x * blockDim.x + threadIdx.x;
    if (m < M4_) {
        int t = m >> 5, b = m & 31;
        int tok = 1;
        if (t > 0) {
            int idx = b * T_ + t - 1;
            tok = is64 ? t32[2 * idx] : t32[idx];
        }
        if (tok < 0) tok = 0;
        if (tok >= V_) tok = V_ - 1;
        g_tok[m] = tok;
    }
}

// ---------------- prep ----------------
__global__ void prep_kernel(const float* __restrict__ enc,
                            const float* __restrict__ E,
                            const float* __restrict__ W_ih,
                            const float* __restrict__ b_ih,
                            const float* __restrict__ b_hh)
{
    long long stride = (long long)gridDim.x * blockDim.x;
    long long tid0 = (long long)blockIdx.x * blockDim.x + threadIdx.x;

    for (long long i = tid0; i < (long long)V_ * H_; i += stride)
        g_Eh[i] = __float2half(E[i]);
    for (long long i = tid0; i < (long long)G_ * H_; i += stride)
        g_Wih_h[i] = __float2half(W_ih[i]);
    for (long long i = tid0; i < G_; i += stride)
        g_biasc[i] = b_ih[i] + b_hh[i];
    for (long long i = tid0; i < (long long)M4_ * H_; i += stride) {
        int m = (int)(i >> 9), k = (int)(i & 511);
        int tok = g_tok[m];
        g_Xe[i] = __float2half(E[(long long)tok * H_ + k]);
    }
    for (long long i = tid0; i < B_ * H_; i += stride)
        g_h0h[i] = __float2half(enc[i]);
    if (tid0 == 0) { g_bar = 0u; g_tile = 0u; }
}

// ---------------- common PTX helpers ----------------
__device__ __forceinline__ uint32_t cvta_s(const void* p) {
    return (uint32_t)__cvta_generic_to_shared(p);
}
__device__ __forceinline__ void cp16(uint32_t d, const void* s) {
    asm volatile("cp.async.cg.shared.global [%0], [%1], 16;" :: "r"(d), "l"(s));
}
__device__ __forceinline__ void ldm4(uint32_t& r0, uint32_t& r1, uint32_t& r2, uint32_t& r3, uint32_t a) {
    asm volatile("ldmatrix.sync.aligned.m8n8.x4.shared.b16 {%0,%1,%2,%3},[%4];"
                 : "=r"(r0), "=r"(r1), "=r"(r2), "=r"(r3) : "r"(a));
}
__device__ __forceinline__ void mma16816(float* c, const uint32_t* a, const uint32_t* b) {
    asm volatile("mma.sync.aligned.m16n8k16.row.col.f32.f16.f16.f32 "
                 "{%0,%1,%2,%3},{%4,%5,%6,%7},{%8,%9},{%0,%1,%2,%3};"
                 : "+f"(c[0]), "+f"(c[1]), "+f"(c[2]), "+f"(c[3])
                 : "r"(a[0]), "r"(a[1]), "r"(a[2]), "r"(a[3]), "r"(b[0]), "r"(b[1]));
}

#define SPAD 40

// ---------------- GEMM1: Xg = Xe @ Wih^T + biasc ----------------
__global__ __launch_bounds__(256, 2)
void hgemm1_kernel()
{
    const __half* A  = g_Xe;
    const __half* Bm = g_Wih_h;
    const int K = H_, N = G_;
    const int m0 = blockIdx.y * 128, n0 = blockIdx.x * 128;

    __shared__ __align__(16) __half As[2][128 * SPAD];
    __shared__ __align__(16) __half Bs[2][128 * SPAD];

    int tid = threadIdx.x, lane = tid & 31, warp = tid >> 5;
    int wm = warp >> 2, wn = warp & 3;

    float acc[4][4][4];
    #pragma unroll
    for (int i = 0; i < 4; i++)
        #pragma unroll
        for (int j = 0; j < 4; j++)
            #pragma unroll
            for (int v = 0; v < 4; v++) acc[i][j][v] = 0.f;

    const __half* gA = A  + (size_t)m0 * K;
    const __half* gB = Bm + (size_t)n0 * K;

    auto load_stage = [&](int s, int ko) {
        #pragma unroll
        for (int id = tid; id < 512; id += 256) {
            int r = id >> 2, c = id & 3;
            cp16(cvta_s(&As[s][r * SPAD + c * 8]), gA + (size_t)r * K + ko + c * 8);
            cp16(cvta_s(&Bs[s][r * SPAD + c * 8]), gB + (size_t)r * K + ko + c * 8);
        }
        asm volatile("cp.async.commit_group;");
    };

    load_stage(0, 0);
    #pragma unroll 1
    for (int it = 0; it < 16; ++it) {
        if (it < 15) load_stage((it + 1) & 1, (it + 1) * 32);
        else asm volatile("cp.async.commit_group;");
        asm volatile("cp.async.wait_group 1;");
        __syncthreads();
        int s = it & 1;
        #pragma unroll
        for (int kk = 0; kk < 32; kk += 16) {
            uint32_t af[4][4], bf[4][2];
            int rsel = lane & 15;
            int csel = kk + ((lane >> 4) << 3);
            #pragma unroll
            for (int mi = 0; mi < 4; mi++) {
                uint32_t a = cvta_s(&As[s][(wm * 64 + mi * 16 + rsel) * SPAD + csel]);
                ldm4(af[mi][0], af[mi][1], af[mi][2], af[mi][3], a);
            }
            #pragma unroll
            for (int p = 0; p < 2; p++) {
                uint32_t r0, r1, r2, r3;
                uint32_t a = cvta_s(&Bs[s][(wn * 32 + p * 16 + rsel) * SPAD + csel]);
                ldm4(r0, r1, r2, r3, a);
                bf[2 * p][0] = r0;     bf[2 * p][1] = r2;
                bf[2 * p + 1][0] = r1; bf[2 * p + 1][1] = r3;
            }
            #pragma unroll
            for (int mi = 0; mi < 4; mi++)
                #pragma unroll
                for (int nj = 0; nj < 4; nj++)
                    mma16816(acc[mi][nj], af[mi], bf[nj]);
        }
        __syncthreads();
    }

    int g = lane >> 2, t4 = lane & 3;
    #pragma unroll
    for (int mi = 0; mi < 4; mi++) {
        #pragma unroll
        for (int nj = 0; nj < 4; nj++) {
            int mr = m0 + wm * 64 + mi * 16 + g;
            int nc = n0 + wn * 32 + nj * 8 + t4 * 2;
            float b0v = g_biasc[nc], b1v = g_biasc[nc + 1];
            g_Xg[(size_t)mr * N + nc]           = acc[mi][nj][0] + b0v;
            g_Xg[(size_t)mr * N + nc + 1]       = acc[mi][nj][1] + b1v;
            g_Xg[(size_t)(mr + 8) * N + nc]     = acc[mi][nj][2] + b0v;
            g_Xg[(size_t)(mr + 8) * N + nc + 1] = acc[mi][nj][3] + b1v;
        }
    }
}

// ---------------- GEMM2 tile worker (device fn): out-tile = Hall @ Eh^T + b_out ----------------
__device__ void gemm2_tile(char* smraw, int m0, int n0,
                           const float* __restrict__ bias, float* __restrict__ C)
{
    __half* As0 = (__half*)smraw;                 // 2 x 128*SPAD
    __half* Bs0 = As0 + 2 * 128 * SPAD;           // 2 x 128*SPAD

    const int K = H_;
    int tid = threadIdx.x, lane = tid & 31, warp = tid >> 5;
    int wm = warp >> 2, wn = warp & 3;

    float acc[4][4][4];
    #pragma unroll
    for (int i = 0; i < 4; i++)
        #pragma unroll
        for (int j = 0; j < 4; j++)
            #pragma unroll
            for (int v = 0; v < 4; v++) acc[i][j][v] = 0.f;

    const __half* gA = g_Hall + (size_t)m0 * K;
    const __half* gB = g_Eh   + (size_t)n0 * K;

    auto load_stage = [&](int s, int ko) {
        __half* As = As0 + s * 128 * SPAD;
        __half* Bs = Bs0 + s * 128 * SPAD;
        #pragma unroll
        for (int id = tid; id < 512; id += 256) {
            int r = id >> 2, c = id & 3;
            cp16(cvta_s(&As[r * SPAD + c * 8]), gA + (size_t)r * K + ko + c * 8);
            cp16(cvta_s(&Bs[r * SPAD + c * 8]), gB + (size_t)r * K + ko + c * 8);
        }
        asm volatile("cp.async.commit_group;");
    };

    load_stage(0, 0);
    #pragma unroll 1
    for (int it = 0; it < 16; ++it) {
        if (it < 15) load_stage((it + 1) & 1, (it + 1) * 32);
        else asm volatile("cp.async.commit_group;");
        asm volatile("cp.async.wait_group 1;");
        __syncthreads();
        int s = it & 1;
        __half* As = As0 + s * 128 * SPAD;
        __half* Bs = Bs0 + s * 128 * SPAD;
        #pragma unroll
        for (int kk = 0; kk < 32; kk += 16) {
            uint32_t af[4][4], bf[4][2];
            int rsel = lane & 15;
            int csel = kk + ((lane >> 4) << 3);
            #pragma unroll
            for (int mi = 0; mi < 4; mi++) {
                uint32_t a = cvta_s(&As[(wm * 64 + mi * 16 + rsel) * SPAD + csel]);
                ldm4(af[mi][0], af[mi][1], af[mi][2], af[mi][3], a);
            }
            #pragma unroll
            for (int p = 0; p < 2; p++) {
                uint32_t r0, r1, r2, r3;
                uint32_t a = cvta_s(&Bs[(wn * 32 + p * 16 + rsel) * SPAD + csel]);
                ldm4(r0, r1, r2, r3, a);
                bf[2 * p][0] = r0;     bf[2 * p][1] = r2;
                bf[2 * p + 1][0] = r1; bf[2 * p + 1][1] = r3;
            }
            #pragma unroll
            for (int mi = 0; mi < 4; mi++)
                #pragma unroll
                for (int nj = 0; nj < 4; nj++)
                    mma16816(acc[mi][nj], af[mi], bf[nj]);
        }
        __syncthreads();
    }

    int g = lane >> 2, t4 = lane & 3;
    #pragma unroll
    for (int mi = 0; mi < 4; mi++) {
        #pragma unroll
        for (int nj = 0; nj < 4; nj++) {
            int mr = m0 + wm * 64 + mi * 16 + g;
            int nc = n0 + wn * 32 + nj * 8 + t4 * 2;
            float b0v = bias[nc], b1v = bias[nc + 1];
            int t1 = mr >> 5, b1 = mr & 31;
            int m2 = mr + 8, t2 = m2 >> 5, b2 = m2 & 31;
            C[((size_t)b1 * T_ + t1) * V_ + nc]     = acc[mi][nj][0] + b0v;
            C[((size_t)b1 * T_ + t1) * V_ + nc + 1] = acc[mi][nj][1] + b1v;
            C[((size_t)b2 * T_ + t2) * V_ + nc]     = acc[mi][nj][2] + b0v;
            C[((size_t)b2 * T_ + t2) * V_ + nc + 1] = acc[mi][nj][3] + b1v;
        }
    }
}

// ---------------- fused recurrence + overlapped GEMM2 ----------------
#define HS_STR 520
#define WS_STR 520
#define P_STR  18
#define LSTM_SMEM ((32 * HS_STR + 16 * WS_STR) * 2 + (8 * 32 * P_STR) * 4)  // 68352

__global__ __launch_bounds__(256, 2)
void fused_kernel(const float* __restrict__ W_hh,
                  const float* __restrict__ enc,
                  const float* __restrict__ b_out,
                  float* __restrict__ out)
{
    extern __shared__ __align__(16) char smraw[];
    __shared__ int s_tile;

    const int tid = threadIdx.x, lane = tid & 31, w = tid >> 5;

    if (blockIdx.x < NB_) {
        // ---------------- recurrence role ----------------
        __half* Hs = (__half*)smraw;
        __half* Ws = Hs + 32 * HS_STR;
        float*  P  = (float*)(Ws + 16 * WS_STR);

        const int cb = blockIdx.x;

        for (int i = tid; i < 16 * 512; i += 256) {
            int r = i >> 9, k = i & 511;
            int q = r >> 2, iu = r & 3;
            Ws[r * WS_STR + k] = __float2half(W_hh[(size_t)((q << 9) + (cb << 2) + iu) * H_ + k]);
        }
        float cst = 0.f;
        if (w < 4) cst = enc[lane * H_ + (cb << 2) + w];

        const int rsel = lane & 15;
        const int csel0 = (w << 6) + ((lane >> 4) << 3);
        const int grp = lane >> 2, t4 = lane & 3;
        __syncthreads();

        for (int t = 0; t < T_; t++) {
            const __half* hin = (t == 0) ? g_h0h : g_Hall + (size_t)(t - 1) * (B_ * H_);
            for (int i = tid; i < B_ * (H_ / 8); i += 256) {
                int b = i >> 6, k8 = i & 63;
                uint4 v = __ldcg((const uint4*)(hin + b * H_ + (k8 << 3)));
                *(uint4*)(Hs + b * HS_STR + (k8 << 3)) = v;
            }
            __syncthreads();

            float acc[2][2][4];
            #pragma unroll
            for (int mi = 0; mi < 2; mi++)
                #pragma unroll
                for (int nj = 0; nj < 2; nj++)
                    #pragma unroll
                    for (int v = 0; v < 4; v++) acc[mi][nj][v] = 0.f;

            #pragma unroll
            for (int kk = 0; kk < 64; kk += 16) {
                int csel = csel0 + kk;
                uint32_t af[2][4], bf[2][2];
                #pragma unroll
                for (int mi = 0; mi < 2; mi++) {
                    uint32_t a = cvta_s(&Hs[(mi * 16 + rsel) * HS_STR + csel]);
                    ldm4(af[mi][0], af[mi][1], af[mi][2], af[mi][3], a);
                }
                {
                    uint32_t r0, r1, r2, r3;
                    uint32_t a = cvta_s(&Ws[rsel * WS_STR + csel]);
                    ldm4(r0, r1, r2, r3, a);
                    bf[0][0] = r0; bf[0][1] = r2;
                    bf[1][0] = r1; bf[1][1] = r3;
                }
                #pragma unroll
                for (int mi = 0; mi < 2; mi++)
                    #pragma unroll
                    for (int nj = 0; nj < 2; nj++)
                        mma16816(acc[mi][nj], af[mi], bf[nj]);
            }

            float* Pw = P + w * 32 * P_STR;
            #pragma unroll
            for (int mi = 0; mi < 2; mi++)
                #pragma unroll
                for (int nj = 0; nj < 2; nj++) {
                    int mbase = mi * 16 + grp, nbase = nj * 8 + t4 * 2;
                    Pw[mbase * P_STR + nbase]           = acc[mi][nj][0];
                    Pw[mbase * P_STR + nbase + 1]       = acc[mi][nj][1];
                    Pw[(mbase + 8) * P_STR + nbase]     = acc[mi][nj][2];
                    Pw[(mbase + 8) * P_STR + nbase + 1] = acc[mi][nj][3];
                }
            __syncthreads();

            if (w < 4) {
                int b = lane;
                float s0 = 0, s1 = 0, s2 = 0, s3 = 0;
                #pragma unroll
                for (int ww = 0; ww < 8; ww++) {
                    const float* Pr = P + (ww * 32 + b) * P_STR;
                    s0 += Pr[w]; s1 += Pr[4 + w]; s2 += Pr[8 + w]; s3 += Pr[12 + w];
                }
                const float* xg = g_Xg + (size_t)(t * B_ + b) * G_ + (cb << 2) + w;
                float gi = s0 + xg[0 * 512];
                float gf = s1 + xg[1 * 512];
                float gg = s2 + xg[2 * 512];
                float go = s3 + xg[3 * 512];
                float i_ = 1.f / (1.f + __expf(-gi));
                float f_ = 1.f / (1.f + __expf(-gf));
                float gv = tanhf(gg);
                float o_ = 1.f / (1.f + __expf(-go));
                cst = f_ * cst + i_ * gv;
                float hv = o_ * tanhf(cst);
                g_Hall[(size_t)(t * B_ + b) * H_ + (cb << 2) + w] = __float2half(hv);
            }
            __syncthreads();
            if (tid == 0) {
                rel_add(&g_bar);
                unsigned tgt = (unsigned)(t + 1) * NB_;
                while (acq_ld(&g_bar) < tgt) { }
            }
            __syncthreads();
        }
        // fall through: join the GEMM2 tile queue
    }

    // ---------------- GEMM2 worker role ----------------
    for (;;) {
        if (tid == 0) s_tile = (int)atomicAdd(&g_tile, 1u);
        __syncthreads();
        int tile = s_tile;
        if (tile >= TILES) break;
        int mt = tile / NTN, nt = tile % NTN;

        if (tid == 0) {
            unsigned need = (unsigned)(4 * mt + 4) * NB_;
            while (acq_ld(&g_bar) < need) __nanosleep(128);
        }
        __syncthreads();

        gemm2_tile(smraw, mt * 128, nt * 128, b_out, out);
        __syncthreads();
    }
}

// ---------------- launch ----------------
extern "C" void kernel_launch(void* const* d_in, const int* in_sizes, int n_in,
                              void* d_out, int out_size)
{
    const float* enc   = (const float*)d_in[0];
    const int*   tgt32 = (const int*)d_in[1];
    const float* E     = (const float*)d_in[2];
    const float* W_ih  = (const float*)d_in[3];
    const float* W_hh  = (const float*)d_in[4];
    const float* b_ih  = (const float*)d_in[5];
    const float* b_hh  = (const float*)d_in[6];
    const float* b_out = (const float*)d_in[7];
    float* out = (float*)d_out;

    tok_kernel<<<M4_ / 256, 256>>>(tgt32);
    prep_kernel<<<4096, 256>>>(enc, E, W_ih, b_ih, b_hh);

    dim3 g0(G_ / 128, M4_ / 128);
    hgemm1_kernel<<<g0, 256>>>();

    cudaFuncSetAttribute(fused_kernel,
                         cudaFuncAttributeMaxDynamicSharedMemorySize, LSTM_SMEM);
    fused_kernel<<<288, 256, LSTM_SMEM>>>(W_hh, enc, b_out, out);
}

// round 8
// speedup vs baseline: 1.9853x; 1.0447x over previous
#include <cuda_runtime.h>
#include <cuda_fp16.h>
#include <cstdint>

#define B_  32
#define T_  128
#define H_  512
#define V_  32000
#define G_  2048      // 4*H
#define M4_ 4096      // B*T
#define NB_ 128       // recurrence CTAs
#define NTM 32        // m-tiles (M4/128)
#define NTN 250       // n-tiles (V/128)
#define TILES (NTM * NTN)

// ---------------- device scratch ----------------
__device__ __align__(16) __half  g_Eh[V_ * H_];
__device__ __align__(16) __half  g_Wih_h[G_ * H_];
__device__ __align__(16) float   g_biasc[G_];
__device__ __align__(16) __half  g_Xe[M4_ * H_];
__device__ __align__(16) float   g_Xg[(size_t)M4_ * G_];
__device__ __align__(16) __half  g_Hall[M4_ * H_];
__device__ __align__(16) __half  g_h0h[B_ * H_];
__device__ __align__(16) int     g_tok[M4_];
__device__ unsigned g_bar;      // recurrence-private barrier counter
__device__ __align__(128) unsigned g_step;   // published completed steps (separate line)
__device__ __align__(128) unsigned g_tile;   // tile queue head (separate line)

// ---------------- sync helpers ----------------
__device__ __forceinline__ void rel_add(unsigned* p) {
    asm volatile("red.release.gpu.global.add.u32 [%0], %1;" :: "l"(p), "r"(1u) : "memory");
}
__device__ __forceinline__ unsigned acq_ld(unsigned* p) {
    unsigned v;
    asm volatile("ld.acquire.gpu.global.u32 %0, [%1];" : "=r"(v) : "l"(p) : "memory");
    return v;
}
__device__ __forceinline__ void rel_st(unsigned* p, unsigned v) {
    asm volatile("st.release.gpu.global.u32 [%0], %1;" :: "l"(p), "r"(v) : "memory");
}

// ---------------- token decode (dtype sniffing) ----------------
__global__ void tok_kernel(const int* __restrict__ t32)
{
    int acc = 0;
    #pragma unroll
    for (int j = 1; j < 128; j += 2) acc |= t32[j];
    bool is64 = (acc == 0);

    int m = blockIdx.x * blockDim.x + threadIdx.x;
    if (m < M4_) {
        int t = m >> 5, b = m & 31;
        int tok = 1;
        if (t > 0) {
            int idx = b * T_ + t - 1;
            tok = is64 ? t32[2 * idx] : t32[idx];
        }
        if (tok < 0) tok = 0;
        if (tok >= V_) tok = V_ - 1;
        g_tok[m] = tok;
    }
}

// ---------------- prep ----------------
__global__ void prep_kernel(const float* __restrict__ enc,
                            const float* __restrict__ E,
                            const float* __restrict__ W_ih,
                            const float* __restrict__ b_ih,
                            const float* __restrict__ b_hh)
{
    long long stride = (long long)gridDim.x * blockDim.x;
    long long tid0 = (long long)blockIdx.x * blockDim.x + threadIdx.x;

    for (long long i = tid0; i < (long long)V_ * H_; i += stride)
        g_Eh[i] = __float2half(E[i]);
    for (long long i = tid0; i < (long long)G_ * H_; i += stride)
        g_Wih_h[i] = __float2half(W_ih[i]);
    for (long long i = tid0; i < G_; i += stride)
        g_biasc[i] = b_ih[i] + b_hh[i];
    for (long long i = tid0; i < (long long)M4_ * H_; i += stride) {
        int m = (int)(i >> 9), k = (int)(i & 511);
        int tok = g_tok[m];
        g_Xe[i] = __float2half(E[(long long)tok * H_ + k]);
    }
    for (long long i = tid0; i < B_ * H_; i += stride)
        g_h0h[i] = __float2half(enc[i]);
    if (tid0 == 0) { g_bar = 0u; g_tile = 0u; g_step = 0u; }
}

// ---------------- common PTX helpers ----------------
__device__ __forceinline__ uint32_t cvta_s(const void* p) {
    return (uint32_t)__cvta_generic_to_shared(p);
}
__device__ __forceinline__ void cp16(uint32_t d, const void* s) {
    asm volatile("cp.async.cg.shared.global [%0], [%1], 16;" :: "r"(d), "l"(s));
}
__device__ __forceinline__ void ldm4(uint32_t& r0, uint32_t& r1, uint32_t& r2, uint32_t& r3, uint32_t a) {
    asm volatile("ldmatrix.sync.aligned.m8n8.x4.shared.b16 {%0,%1,%2,%3},[%4];"
                 : "=r"(r0), "=r"(r1), "=r"(r2), "=r"(r3) : "r"(a));
}
__device__ __forceinline__ void mma16816(float* c, const uint32_t* a, const uint32_t* b) {
    asm volatile("mma.sync.aligned.m16n8k16.row.col.f32.f16.f16.f32 "
                 "{%0,%1,%2,%3},{%4,%5,%6,%7},{%8,%9},{%0,%1,%2,%3};"
                 : "+f"(c[0]), "+f"(c[1]), "+f"(c[2]), "+f"(c[3])
                 : "r"(a[0]), "r"(a[1]), "r"(a[2]), "r"(a[3]), "r"(b[0]), "r"(b[1]));
}

#define SPAD 40

// ---------------- GEMM1: Xg = Xe @ Wih^T + biasc (proven, unchanged) ----------------
__global__ __launch_bounds__(256, 2)
void hgemm1_kernel()
{
    const __half* A  = g_Xe;
    const __half* Bm = g_Wih_h;
    const int K = H_, N = G_;
    const int m0 = blockIdx.y * 128, n0 = blockIdx.x * 128;

    __shared__ __align__(16) __half As[2][128 * SPAD];
    __shared__ __align__(16) __half Bs[2][128 * SPAD];

    int tid = threadIdx.x, lane = tid & 31, warp = tid >> 5;
    int wm = warp >> 2, wn = warp & 3;

    float acc[4][4][4];
    #pragma unroll
    for (int i = 0; i < 4; i++)
        #pragma unroll
        for (int j = 0; j < 4; j++)
            #pragma unroll
            for (int v = 0; v < 4; v++) acc[i][j][v] = 0.f;

    const __half* gA = A  + (size_t)m0 * K;
    const __half* gB = Bm + (size_t)n0 * K;

    auto load_stage = [&](int s, int ko) {
        #pragma unroll
        for (int id = tid; id < 512; id += 256) {
            int r = id >> 2, c = id & 3;
            cp16(cvta_s(&As[s][r * SPAD + c * 8]), gA + (size_t)r * K + ko + c * 8);
            cp16(cvta_s(&Bs[s][r * SPAD + c * 8]), gB + (size_t)r * K + ko + c * 8);
        }
        asm volatile("cp.async.commit_group;");
    };

    load_stage(0, 0);
    #pragma unroll 1
    for (int it = 0; it < 16; ++it) {
        if (it < 15) load_stage((it + 1) & 1, (it + 1) * 32);
        else asm volatile("cp.async.commit_group;");
        asm volatile("cp.async.wait_group 1;");
        __syncthreads();
        int s = it & 1;
        #pragma unroll
        for (int kk = 0; kk < 32; kk += 16) {
            uint32_t af[4][4], bf[4][2];
            int rsel = lane & 15;
            int csel = kk + ((lane >> 4) << 3);
            #pragma unroll
            for (int mi = 0; mi < 4; mi++) {
                uint32_t a = cvta_s(&As[s][(wm * 64 + mi * 16 + rsel) * SPAD + csel]);
                ldm4(af[mi][0], af[mi][1], af[mi][2], af[mi][3], a);
            }
            #pragma unroll
            for (int p = 0; p < 2; p++) {
                uint32_t r0, r1, r2, r3;
                uint32_t a = cvta_s(&Bs[s][(wn * 32 + p * 16 + rsel) * SPAD + csel]);
                ldm4(r0, r1, r2, r3, a);
                bf[2 * p][0] = r0;     bf[2 * p][1] = r2;
                bf[2 * p + 1][0] = r1; bf[2 * p + 1][1] = r3;
            }
            #pragma unroll
            for (int mi = 0; mi < 4; mi++)
                #pragma unroll
                for (int nj = 0; nj < 4; nj++)
                    mma16816(acc[mi][nj], af[mi], bf[nj]);
        }
        __syncthreads();
    }

    int g = lane >> 2, t4 = lane & 3;
    #pragma unroll
    for (int mi = 0; mi < 4; mi++) {
        #pragma unroll
        for (int nj = 0; nj < 4; nj++) {
            int mr = m0 + wm * 64 + mi * 16 + g;
            int nc = n0 + wn * 32 + nj * 8 + t4 * 2;
            float b0v = g_biasc[nc], b1v = g_biasc[nc + 1];
            g_Xg[(size_t)mr * N + nc]           = acc[mi][nj][0] + b0v;
            g_Xg[(size_t)mr * N + nc + 1]       = acc[mi][nj][1] + b1v;
            g_Xg[(size_t)(mr + 8) * N + nc]     = acc[mi][nj][2] + b0v;
            g_Xg[(size_t)(mr + 8) * N + nc + 1] = acc[mi][nj][3] + b1v;
        }
    }
}

// ---------------- GEMM2 tile worker: K-chunk 64, double-buffered ----------------
#define SPD2 72   // 64 data halfs + 8 pad per smem row

__device__ void gemm2_tile(char* smraw, int m0, int n0,
                           const float* __restrict__ bias, float* __restrict__ C)
{
    __half* As0 = (__half*)smraw;                 // 2 x 128*SPD2
    __half* Bs0 = As0 + 2 * 128 * SPD2;           // 2 x 128*SPD2

    const int K = H_;
    int tid = threadIdx.x, lane = tid & 31, warp = tid >> 5;
    int wm = warp >> 2, wn = warp & 3;

    float acc[4][4][4];
    #pragma unroll
    for (int i = 0; i < 4; i++)
        #pragma unroll
        for (int j = 0; j < 4; j++)
            #pragma unroll
            for (int v = 0; v < 4; v++) acc[i][j][v] = 0.f;

    const __half* gA = g_Hall + (size_t)m0 * K;
    const __half* gB = g_Eh   + (size_t)n0 * K;

    auto load_stage = [&](int s, int ko) {
        __half* As = As0 + s * 128 * SPD2;
        __half* Bs = Bs0 + s * 128 * SPD2;
        #pragma unroll
        for (int id = tid; id < 1024; id += 256) {
            int r = id >> 3, c = id & 7;
            cp16(cvta_s(&As[r * SPD2 + c * 8]), gA + (size_t)r * K + ko + c * 8);
        }
        #pragma unroll
        for (int id = tid; id < 1024; id += 256) {
            int r = id >> 3, c = id & 7;
            cp16(cvta_s(&Bs[r * SPD2 + c * 8]), gB + (size_t)r * K + ko + c * 8);
        }
        asm volatile("cp.async.commit_group;");
    };

    load_stage(0, 0);
    #pragma unroll 1
    for (int it = 0; it < 8; ++it) {              // K=512 / 64
        if (it < 7) load_stage((it + 1) & 1, (it + 1) * 64);
        else asm volatile("cp.async.commit_group;");
        asm volatile("cp.async.wait_group 1;");
        __syncthreads();
        int s = it & 1;
        __half* As = As0 + s * 128 * SPD2;
        __half* Bs = Bs0 + s * 128 * SPD2;
        #pragma unroll
        for (int kk = 0; kk < 64; kk += 16) {
            uint32_t af[4][4], bf[4][2];
            int rsel = lane & 15;
            int csel = kk + ((lane >> 4) << 3);
            #pragma unroll
            for (int mi = 0; mi < 4; mi++) {
                uint32_t a = cvta_s(&As[(wm * 64 + mi * 16 + rsel) * SPD2 + csel]);
                ldm4(af[mi][0], af[mi][1], af[mi][2], af[mi][3], a);
            }
            #pragma unroll
            for (int p = 0; p < 2; p++) {
                uint32_t r0, r1, r2, r3;
                uint32_t a = cvta_s(&Bs[(wn * 32 + p * 16 + rsel) * SPD2 + csel]);
                ldm4(r0, r1, r2, r3, a);
                bf[2 * p][0] = r0;     bf[2 * p][1] = r2;
                bf[2 * p + 1][0] = r1; bf[2 * p + 1][1] = r3;
            }
            #pragma unroll
            for (int mi = 0; mi < 4; mi++)
                #pragma unroll
                for (int nj = 0; nj < 4; nj++)
                    mma16816(acc[mi][nj], af[mi], bf[nj]);
        }
        __syncthreads();
    }

    int g = lane >> 2, t4 = lane & 3;
    #pragma unroll
    for (int mi = 0; mi < 4; mi++) {
        #pragma unroll
        for (int nj = 0; nj < 4; nj++) {
            int mr = m0 + wm * 64 + mi * 16 + g;
            int nc = n0 + wn * 32 + nj * 8 + t4 * 2;
            float b0v = bias[nc], b1v = bias[nc + 1];
            int t1 = mr >> 5, b1 = mr & 31;
            int m2 = mr + 8, t2 = m2 >> 5, b2 = m2 & 31;
            C[((size_t)b1 * T_ + t1) * V_ + nc]     = acc[mi][nj][0] + b0v;
            C[((size_t)b1 * T_ + t1) * V_ + nc + 1] = acc[mi][nj][1] + b1v;
            C[((size_t)b2 * T_ + t2) * V_ + nc]     = acc[mi][nj][2] + b0v;
            C[((size_t)b2 * T_ + t2) * V_ + nc + 1] = acc[mi][nj][3] + b1v;
        }
    }
}

// ---------------- fused recurrence + overlapped GEMM2 ----------------
#define HS_STR 520
#define WS_STR 520
#define P_STR  18
#define REC_SMEM ((32 * HS_STR + 16 * WS_STR) * 2 + (8 * 32 * P_STR) * 4)   // 68352
#define GEMM_SMEM (2 * 2 * 128 * SPD2 * 2)                                   // 73728
#define FUSED_SMEM (GEMM_SMEM > REC_SMEM ? GEMM_SMEM : REC_SMEM)

__global__ __launch_bounds__(256, 2)
void fused_kernel(const float* __restrict__ W_hh,
                  const float* __restrict__ enc,
                  const float* __restrict__ b_out,
                  float* __restrict__ out)
{
    extern __shared__ __align__(16) char smraw[];
    __shared__ int s_tile;

    const int tid = threadIdx.x, lane = tid & 31, w = tid >> 5;

    if (blockIdx.x < NB_) {
        // ---------------- recurrence role ----------------
        __half* Hs = (__half*)smraw;
        __half* Ws = Hs + 32 * HS_STR;
        float*  P  = (float*)(Ws + 16 * WS_STR);

        const int cb = blockIdx.x;

        for (int i = tid; i < 16 * 512; i += 256) {
            int r = i >> 9, k = i & 511;
            int q = r >> 2, iu = r & 3;
            Ws[r * WS_STR + k] = __float2half(W_hh[(size_t)((q << 9) + (cb << 2) + iu) * H_ + k]);
        }
        float cst = 0.f;
        if (w < 4) cst = enc[lane * H_ + (cb << 2) + w];

        const int rsel = lane & 15;
        const int csel0 = (w << 6) + ((lane >> 4) << 3);
        const int grp = lane >> 2, t4 = lane & 3;
        __syncthreads();

        for (int t = 0; t < T_; t++) {
            // prefetch Xg early (independent of h) so L2 latency overlaps the MMA
            float x0 = 0.f, x1 = 0.f, x2 = 0.f, x3 = 0.f;
            if (w < 4) {
                const float* xg = g_Xg + (size_t)(t * B_ + lane) * G_ + (cb << 2) + w;
                x0 = __ldcg(xg);
                x1 = __ldcg(xg + 512);
                x2 = __ldcg(xg + 1024);
                x3 = __ldcg(xg + 1536);
            }

            const __half* hin = (t == 0) ? g_h0h : g_Hall + (size_t)(t - 1) * (B_ * H_);
            for (int i = tid; i < B_ * (H_ / 8); i += 256) {
                int b = i >> 6, k8 = i & 63;
                uint4 v = __ldcg((const uint4*)(hin + b * H_ + (k8 << 3)));
                *(uint4*)(Hs + b * HS_STR + (k8 << 3)) = v;
            }
            __syncthreads();

            float acc[2][2][4];
            #pragma unroll
            for (int mi = 0; mi < 2; mi++)
                #pragma unroll
                for (int nj = 0; nj < 2; nj++)
                    #pragma unroll
                    for (int v = 0; v < 4; v++) acc[mi][nj][v] = 0.f;

            #pragma unroll
            for (int kk = 0; kk < 64; kk += 16) {
                int csel = csel0 + kk;
                uint32_t af[2][4], bf[2][2];
                #pragma unroll
                for (int mi = 0; mi < 2; mi++) {
                    uint32_t a = cvta_s(&Hs[(mi * 16 + rsel) * HS_STR + csel]);
                    ldm4(af[mi][0], af[mi][1], af[mi][2], af[mi][3], a);
                }
                {
                    uint32_t r0, r1, r2, r3;
                    uint32_t a = cvta_s(&Ws[rsel * WS_STR + csel]);
                    ldm4(r0, r1, r2, r3, a);
                    bf[0][0] = r0; bf[0][1] = r2;
                    bf[1][0] = r1; bf[1][1] = r3;
                }
                #pragma unroll
                for (int mi = 0; mi < 2; mi++)
                    #pragma unroll
                    for (int nj = 0; nj < 2; nj++)
                        mma16816(acc[mi][nj], af[mi], bf[nj]);
            }

            float* Pw = P + w * 32 * P_STR;
            #pragma unroll
            for (int mi = 0; mi < 2; mi++)
                #pragma unroll
                for (int nj = 0; nj < 2; nj++) {
                    int mbase = mi * 16 + grp, nbase = nj * 8 + t4 * 2;
                    Pw[mbase * P_STR + nbase]           = acc[mi][nj][0];
                    Pw[mbase * P_STR + nbase + 1]       = acc[mi][nj][1];
                    Pw[(mbase + 8) * P_STR + nbase]     = acc[mi][nj][2];
                    Pw[(mbase + 8) * P_STR + nbase + 1] = acc[mi][nj][3];
                }
            __syncthreads();

            if (w < 4) {
                int b = lane;
                float s0 = 0, s1 = 0, s2 = 0, s3 = 0;
                #pragma unroll
                for (int ww = 0; ww < 8; ww++) {
                    const float* Pr = P + (ww * 32 + b) * P_STR;
                    s0 += Pr[w]; s1 += Pr[4 + w]; s2 += Pr[8 + w]; s3 += Pr[12 + w];
                }
                float gi = s0 + x0;
                float gf = s1 + x1;
                float gg = s2 + x2;
                float go = s3 + x3;
                float i_ = 1.f / (1.f + __expf(-gi));
                float f_ = 1.f / (1.f + __expf(-gf));
                float gv = tanhf(gg);
                float o_ = 1.f / (1.f + __expf(-go));
                cst = f_ * cst + i_ * gv;
                float hv = o_ * tanhf(cst);
                g_Hall[(size_t)(t * B_ + b) * H_ + (cb << 2) + w] = __float2half(hv);
            }
            __syncthreads();
            if (tid == 0) {
                rel_add(&g_bar);
                unsigned tgt = (unsigned)(t + 1) * NB_;
                while (acq_ld(&g_bar) < tgt) { }
                if (cb == 0) rel_st(&g_step, (unsigned)(t + 1));
            }
            __syncthreads();
        }
        // fall through: join the GEMM2 tile queue
    }

    // ---------------- GEMM2 worker role ----------------
    for (;;) {
        if (tid == 0) s_tile = (int)atomicAdd(&g_tile, 1u);
        __syncthreads();
        int tile = s_tile;
        if (tile >= TILES) break;
        int mt = tile / NTN, nt = tile % NTN;

        if (tid == 0) {
            unsigned need = (unsigned)(4 * mt + 4);
            while (acq_ld(&g_step) < need) __nanosleep(256);
        }
        __syncthreads();

        gemm2_tile(smraw, mt * 128, nt * 128, b_out, out);
        __syncthreads();
    }
}

// ---------------- launch ----------------
extern "C" void kernel_launch(void* const* d_in, const int* in_sizes, int n_in,
                              void* d_out, int out_size)
{
    const float* enc   = (const float*)d_in[0];
    const int*   tgt32 = (const int*)d_in[1];
    const float* E     = (const float*)d_in[2];
    const float* W_ih  = (const float*)d_in[3];
    const float* W_hh  = (const float*)d_in[4];
    const float* b_ih  = (const float*)d_in[5];
    const float* b_hh  = (const float*)d_in[6];
    const float* b_out = (const float*)d_in[7];
    float* out = (float*)d_out;

    tok_kernel<<<M4_ / 256, 256>>>(tgt32);
    prep_kernel<<<4096, 256>>>(enc, E, W_ih, b_ih, b_hh);

    dim3 g0(G_ / 128, M4_ / 128);
    hgemm1_kernel<<<g0, 256>>>();

    cudaFuncSetAttribute(fused_kernel,
                         cudaFuncAttributeMaxDynamicSharedMemorySize, FUSED_SMEM);
    fused_kernel<<<288, 256, FUSED_SMEM>>>(W_hh, enc, b_out, out);
}

// round 9
// speedup vs baseline: 1.9978x; 1.0063x over previous
#include <cuda_runtime.h>
#include <cuda_fp16.h>
#include <cstdint>

#define B_  32
#define T_  128
#define H_  512
#define V_  32000
#define G_  2048      // 4*H
#define M4_ 4096      // B*T
#define NBR 64        // recurrence CTAs (8 units each)
#define NTM 32        // m-tiles (M4/128)
#define NTN 250       // n-tiles (V/128)
#define TILES (NTM * NTN)

// ---------------- device scratch ----------------
__device__ __align__(16) __half  g_Eh[V_ * H_];
__device__ __align__(16) __half  g_Wih_h[G_ * H_];
__device__ __align__(16) float   g_biasc[G_];
__device__ __align__(16) __half  g_Xe[M4_ * H_];
__device__ __align__(16) float   g_Xg[(size_t)M4_ * G_];
__device__ __align__(16) __half  g_Hall[M4_ * H_];
__device__ __align__(16) __half  g_h0h[B_ * H_];
__device__ __align__(16) int     g_tok[M4_];
__device__ unsigned g_bar;                   // recurrence-private barrier counter
__device__ __align__(128) unsigned g_step;   // published completed steps
__device__ __align__(128) unsigned g_tile;   // tile queue head

// ---------------- sync helpers ----------------
__device__ __forceinline__ void rel_add(unsigned* p) {
    asm volatile("red.release.gpu.global.add.u32 [%0], %1;" :: "l"(p), "r"(1u) : "memory");
}
__device__ __forceinline__ unsigned acq_ld(unsigned* p) {
    unsigned v;
    asm volatile("ld.acquire.gpu.global.u32 %0, [%1];" : "=r"(v) : "l"(p) : "memory");
    return v;
}
__device__ __forceinline__ void rel_st(unsigned* p, unsigned v) {
    asm volatile("st.release.gpu.global.u32 [%0], %1;" :: "l"(p), "r"(v) : "memory");
}

// ---------------- token decode (dtype sniffing) ----------------
__global__ void tok_kernel(const int* __restrict__ t32)
{
    int acc = 0;
    #pragma unroll
    for (int j = 1; j < 128; j += 2) acc |= t32[j];
    bool is64 = (acc == 0);

    int m = blockIdx.x * blockDim.x + threadIdx.x;
    if (m < M4_) {
        int t = m >> 5, b = m & 31;
        int tok = 1;
        if (t > 0) {
            int idx = b * T_ + t - 1;
            tok = is64 ? t32[2 * idx] : t32[idx];
        }
        if (tok < 0) tok = 0;
        if (tok >= V_) tok = V_ - 1;
        g_tok[m] = tok;
    }
}

// ---------------- prep ----------------
__global__ void prep_kernel(const float* __restrict__ enc,
                            const float* __restrict__ E,
                            const float* __restrict__ W_ih,
                            const float* __restrict__ b_ih,
                            const float* __restrict__ b_hh)
{
    long long stride = (long long)gridDim.x * blockDim.x;
    long long tid0 = (long long)blockIdx.x * blockDim.x + threadIdx.x;

    for (long long i = tid0; i < (long long)V_ * H_; i += stride)
        g_Eh[i] = __float2half(E[i]);
    for (long long i = tid0; i < (long long)G_ * H_; i += stride)
        g_Wih_h[i] = __float2half(W_ih[i]);
    for (long long i = tid0; i < G_; i += stride)
        g_biasc[i] = b_ih[i] + b_hh[i];
    for (long long i = tid0; i < (long long)M4_ * H_; i += stride) {
        int m = (int)(i >> 9), k = (int)(i & 511);
        int tok = g_tok[m];
        g_Xe[i] = __float2half(E[(long long)tok * H_ + k]);
    }
    for (long long i = tid0; i < B_ * H_; i += stride)
        g_h0h[i] = __float2half(enc[i]);
    if (tid0 == 0) { g_bar = 0u; g_tile = 0u; g_step = 0u; }
}

// ---------------- common PTX helpers ----------------
__device__ __forceinline__ uint32_t cvta_s(const void* p) {
    return (uint32_t)__cvta_generic_to_shared(p);
}
__device__ __forceinline__ void cp16(uint32_t d, const void* s) {
    asm volatile("cp.async.cg.shared.global [%0], [%1], 16;" :: "r"(d), "l"(s));
}
__device__ __forceinline__ void ldm4(uint32_t& r0, uint32_t& r1, uint32_t& r2, uint32_t& r3, uint32_t a) {
    asm volatile("ldmatrix.sync.aligned.m8n8.x4.shared.b16 {%0,%1,%2,%3},[%4];"
                 : "=r"(r0), "=r"(r1), "=r"(r2), "=r"(r3) : "r"(a));
}
__device__ __forceinline__ void mma16816(float* c, const uint32_t* a, const uint32_t* b) {
    asm volatile("mma.sync.aligned.m16n8k16.row.col.f32.f16.f16.f32 "
                 "{%0,%1,%2,%3},{%4,%5,%6,%7},{%8,%9},{%0,%1,%2,%3};"
                 : "+f"(c[0]), "+f"(c[1]), "+f"(c[2]), "+f"(c[3])
                 : "r"(a[0]), "r"(a[1]), "r"(a[2]), "r"(a[3]), "r"(b[0]), "r"(b[1]));
}

#define SPAD 40

// ---------------- GEMM1: Xg = Xe @ Wih^T + biasc (proven, unchanged) ----------------
__global__ __launch_bounds__(256, 2)
void hgemm1_kernel()
{
    const __half* A  = g_Xe;
    const __half* Bm = g_Wih_h;
    const int K = H_, N = G_;
    const int m0 = blockIdx.y * 128, n0 = blockIdx.x * 128;

    __shared__ __align__(16) __half As[2][128 * SPAD];
    __shared__ __align__(16) __half Bs[2][128 * SPAD];

    int tid = threadIdx.x, lane = tid & 31, warp = tid >> 5;
    int wm = warp >> 2, wn = warp & 3;

    float acc[4][4][4];
    #pragma unroll
    for (int i = 0; i < 4; i++)
        #pragma unroll
        for (int j = 0; j < 4; j++)
            #pragma unroll
            for (int v = 0; v < 4; v++) acc[i][j][v] = 0.f;

    const __half* gA = A  + (size_t)m0 * K;
    const __half* gB = Bm + (size_t)n0 * K;

    auto load_stage = [&](int s, int ko) {
        #pragma unroll
        for (int id = tid; id < 512; id += 256) {
            int r = id >> 2, c = id & 3;
            cp16(cvta_s(&As[s][r * SPAD + c * 8]), gA + (size_t)r * K + ko + c * 8);
            cp16(cvta_s(&Bs[s][r * SPAD + c * 8]), gB + (size_t)r * K + ko + c * 8);
        }
        asm volatile("cp.async.commit_group;");
    };

    load_stage(0, 0);
    #pragma unroll 1
    for (int it = 0; it < 16; ++it) {
        if (it < 15) load_stage((it + 1) & 1, (it + 1) * 32);
        else asm volatile("cp.async.commit_group;");
        asm volatile("cp.async.wait_group 1;");
        __syncthreads();
        int s = it & 1;
        #pragma unroll
        for (int kk = 0; kk < 32; kk += 16) {
            uint32_t af[4][4], bf[4][2];
            int rsel = lane & 15;
            int csel = kk + ((lane >> 4) << 3);
            #pragma unroll
            for (int mi = 0; mi < 4; mi++) {
                uint32_t a = cvta_s(&As[s][(wm * 64 + mi * 16 + rsel) * SPAD + csel]);
                ldm4(af[mi][0], af[mi][1], af[mi][2], af[mi][3], a);
            }
            #pragma unroll
            for (int p = 0; p < 2; p++) {
                uint32_t r0, r1, r2, r3;
                uint32_t a = cvta_s(&Bs[s][(wn * 32 + p * 16 + rsel) * SPAD + csel]);
                ldm4(r0, r1, r2, r3, a);
                bf[2 * p][0] = r0;     bf[2 * p][1] = r2;
                bf[2 * p + 1][0] = r1; bf[2 * p + 1][1] = r3;
            }
            #pragma unroll
            for (int mi = 0; mi < 4; mi++)
                #pragma unroll
                for (int nj = 0; nj < 4; nj++)
                    mma16816(acc[mi][nj], af[mi], bf[nj]);
        }
        __syncthreads();
    }

    int g = lane >> 2, t4 = lane & 3;
    #pragma unroll
    for (int mi = 0; mi < 4; mi++) {
        #pragma unroll
        for (int nj = 0; nj < 4; nj++) {
            int mr = m0 + wm * 64 + mi * 16 + g;
            int nc = n0 + wn * 32 + nj * 8 + t4 * 2;
            float b0v = g_biasc[nc], b1v = g_biasc[nc + 1];
            g_Xg[(size_t)mr * N + nc]           = acc[mi][nj][0] + b0v;
            g_Xg[(size_t)mr * N + nc + 1]       = acc[mi][nj][1] + b1v;
            g_Xg[(size_t)(mr + 8) * N + nc]     = acc[mi][nj][2] + b0v;
            g_Xg[(size_t)(mr + 8) * N + nc + 1] = acc[mi][nj][3] + b1v;
        }
    }
}

// ---------------- GEMM2 tile worker: K-chunk 64, double-buffered ----------------
#define SPD2 72

__device__ void gemm2_tile(char* smraw, int m0, int n0,
                           const float* __restrict__ bias, float* __restrict__ C)
{
    __half* As0 = (__half*)smraw;
    __half* Bs0 = As0 + 2 * 128 * SPD2;

    const int K = H_;
    int tid = threadIdx.x, lane = tid & 31, warp = tid >> 5;
    int wm = warp >> 2, wn = warp & 3;

    float acc[4][4][4];
    #pragma unroll
    for (int i = 0; i < 4; i++)
        #pragma unroll
        for (int j = 0; j < 4; j++)
            #pragma unroll
            for (int v = 0; v < 4; v++) acc[i][j][v] = 0.f;

    const __half* gA = g_Hall + (size_t)m0 * K;
    const __half* gB = g_Eh   + (size_t)n0 * K;

    auto load_stage = [&](int s, int ko) {
        __half* As = As0 + s * 128 * SPD2;
        __half* Bs = Bs0 + s * 128 * SPD2;
        #pragma unroll
        for (int id = tid; id < 1024; id += 256) {
            int r = id >> 3, c = id & 7;
            cp16(cvta_s(&As[r * SPD2 + c * 8]), gA + (size_t)r * K + ko + c * 8);
        }
        #pragma unroll
        for (int id = tid; id < 1024; id += 256) {
            int r = id >> 3, c = id & 7;
            cp16(cvta_s(&Bs[r * SPD2 + c * 8]), gB + (size_t)r * K + ko + c * 8);
        }
        asm volatile("cp.async.commit_group;");
    };

    load_stage(0, 0);
    #pragma unroll 1
    for (int it = 0; it < 8; ++it) {
        if (it < 7) load_stage((it + 1) & 1, (it + 1) * 64);
        else asm volatile("cp.async.commit_group;");
        asm volatile("cp.async.wait_group 1;");
        __syncthreads();
        int s = it & 1;
        __half* As = As0 + s * 128 * SPD2;
        __half* Bs = Bs0 + s * 128 * SPD2;
        #pragma unroll
        for (int kk = 0; kk < 64; kk += 16) {
            uint32_t af[4][4], bf[4][2];
            int rsel = lane & 15;
            int csel = kk + ((lane >> 4) << 3);
            #pragma unroll
            for (int mi = 0; mi < 4; mi++) {
                uint32_t a = cvta_s(&As[(wm * 64 + mi * 16 + rsel) * SPD2 + csel]);
                ldm4(af[mi][0], af[mi][1], af[mi][2], af[mi][3], a);
            }
            #pragma unroll
            for (int p = 0; p < 2; p++) {
                uint32_t r0, r1, r2, r3;
                uint32_t a = cvta_s(&Bs[(wn * 32 + p * 16 + rsel) * SPD2 + csel]);
                ldm4(r0, r1, r2, r3, a);
                bf[2 * p][0] = r0;     bf[2 * p][1] = r2;
                bf[2 * p + 1][0] = r1; bf[2 * p + 1][1] = r3;
            }
            #pragma unroll
            for (int mi = 0; mi < 4; mi++)
                #pragma unroll
                for (int nj = 0; nj < 4; nj++)
                    mma16816(acc[mi][nj], af[mi], bf[nj]);
        }
        __syncthreads();
    }

    int g = lane >> 2, t4 = lane & 3;
    #pragma unroll
    for (int mi = 0; mi < 4; mi++) {
        #pragma unroll
        for (int nj = 0; nj < 4; nj++) {
            int mr = m0 + wm * 64 + mi * 16 + g;
            int nc = n0 + wn * 32 + nj * 8 + t4 * 2;
            float b0v = bias[nc], b1v = bias[nc + 1];
            int t1 = mr >> 5, b1 = mr & 31;
            int m2 = mr + 8, t2 = m2 >> 5, b2 = m2 & 31;
            C[((size_t)b1 * T_ + t1) * V_ + nc]     = acc[mi][nj][0] + b0v;
            C[((size_t)b1 * T_ + t1) * V_ + nc + 1] = acc[mi][nj][1] + b1v;
            C[((size_t)b2 * T_ + t2) * V_ + nc]     = acc[mi][nj][2] + b0v;
            C[((size_t)b2 * T_ + t2) * V_ + nc + 1] = acc[mi][nj][3] + b1v;
        }
    }
}

// ---------------- fused: 64-CTA recurrence + 224-CTA overlapped GEMM2 ----------------
// Recurrence CTA cb owns units cb*8..cb*8+7 -> 32 gate rows (r = q*8+iu).
// Per step: gates[32b][32r] = h[32x512] @ Wc[32x512]^T, 8 warps k-split 64.
// Region0 (33.8KB) holds Hs (h staging) during MMA, then aliases P (partials).
#define HS_STR 520
#define WS_STR 520
#define PSTR   33
#define REG0_B 33792                     // max(Hs 33280, P 8*32*33*4=33792), 16-aligned
#define REC_SMEM (REG0_B + 32 * WS_STR * 2)          // 67072
#define GEMM_SMEM (2 * 2 * 128 * SPD2 * 2)           // 73728
#define FUSED_SMEM (GEMM_SMEM > REC_SMEM ? GEMM_SMEM : REC_SMEM)

__global__ __launch_bounds__(256, 2)
void fused_kernel(const float* __restrict__ W_hh,
                  const float* __restrict__ enc,
                  const float* __restrict__ b_out,
                  float* __restrict__ out)
{
    extern __shared__ __align__(16) char smraw[];
    __shared__ int s_tile;

    const int tid = threadIdx.x, lane = tid & 31, w = tid >> 5;

    if (blockIdx.x < NBR) {
        // ---------------- recurrence role ----------------
        __half* Hs = (__half*)smraw;                 // 32 x 520 halfs
        float*  P  = (float*)smraw;                  // aliases Hs after MMA
        __half* Ws = (__half*)(smraw + REG0_B);      // 32 x 520 halfs

        const int cb = blockIdx.x;
        const int u0 = cb << 3;                      // first unit

        // W rows: r = q*8+iu  ->  W_hh row q*512 + u0 + iu
        for (int i = tid; i < 32 * 512; i += 256) {
            int r = i >> 9, k = i & 511;
            int q = r >> 3, iu = r & 7;
            Ws[r * WS_STR + k] = __float2half(W_hh[(size_t)((q << 9) + u0 + iu) * H_ + k]);
        }
        // every thread: b = lane, unit = w
        float cst = enc[lane * H_ + u0 + w];

        const int rsel = lane & 15;
        const int csel0 = (w << 6) + ((lane >> 4) << 3);
        const int grp = lane >> 2, t4 = lane & 3;
        __syncthreads();

        for (int t = 0; t < T_; t++) {
            // prefetch Xg (independent of h)
            const float* xg = g_Xg + (size_t)(t * B_ + lane) * G_ + u0 + w;
            float x0 = __ldcg(xg);
            float x1 = __ldcg(xg + 512);
            float x2 = __ldcg(xg + 1024);
            float x3 = __ldcg(xg + 1536);

            const __half* hin = (t == 0) ? g_h0h : g_Hall + (size_t)(t - 1) * (B_ * H_);
            for (int i = tid; i < B_ * (H_ / 8); i += 256) {
                int b = i >> 6, k8 = i & 63;
                uint4 v = __ldcg((const uint4*)(hin + b * H_ + (k8 << 3)));
                *(uint4*)(Hs + b * HS_STR + (k8 << 3)) = v;
            }
            __syncthreads();

            float acc[2][4][4];
            #pragma unroll
            for (int mi = 0; mi < 2; mi++)
                #pragma unroll
                for (int nj = 0; nj < 4; nj++)
                    #pragma unroll
                    for (int v = 0; v < 4; v++) acc[mi][nj][v] = 0.f;

            #pragma unroll
            for (int kk = 0; kk < 64; kk += 16) {
                int csel = csel0 + kk;
                uint32_t af[2][4], bf[4][2];
                #pragma unroll
                for (int mi = 0; mi < 2; mi++) {
                    uint32_t a = cvta_s(&Hs[(mi * 16 + rsel) * HS_STR + csel]);
                    ldm4(af[mi][0], af[mi][1], af[mi][2], af[mi][3], a);
                }
                #pragma unroll
                for (int p = 0; p < 2; p++) {
                    uint32_t r0, r1, r2, r3;
                    uint32_t a = cvta_s(&Ws[(p * 16 + rsel) * WS_STR + csel]);
                    ldm4(r0, r1, r2, r3, a);
                    bf[2 * p][0] = r0;     bf[2 * p][1] = r2;
                    bf[2 * p + 1][0] = r1; bf[2 * p + 1][1] = r3;
                }
                #pragma unroll
                for (int mi = 0; mi < 2; mi++)
                    #pragma unroll
                    for (int nj = 0; nj < 4; nj++)
                        mma16816(acc[mi][nj], af[mi], bf[nj]);
            }
            __syncthreads();   // all ldmatrix reads of Hs done -> safe to alias P

            float* Pw = P + w * 32 * PSTR;
            #pragma unroll
            for (int mi = 0; mi < 2; mi++)
                #pragma unroll
                for (int nj = 0; nj < 4; nj++) {
                    int mbase = mi * 16 + grp, nbase = nj * 8 + t4 * 2;
                    Pw[mbase * PSTR + nbase]           = acc[mi][nj][0];
                    Pw[mbase * PSTR + nbase + 1]       = acc[mi][nj][1];
                    Pw[(mbase + 8) * PSTR + nbase]     = acc[mi][nj][2];
                    Pw[(mbase + 8) * PSTR + nbase + 1] = acc[mi][nj][3];
                }
            __syncthreads();

            // all 256 threads: b = lane, unit iu = w; n-col = q*8 + w
            {
                int b = lane;
                float s0 = 0, s1 = 0, s2 = 0, s3 = 0;
                #pragma unroll
                for (int ww = 0; ww < 8; ww++) {
                    const float* Pr = P + (ww * 32 + b) * PSTR;
                    s0 += Pr[0 * 8 + w];
                    s1 += Pr[1 * 8 + w];
                    s2 += Pr[2 * 8 + w];
                    s3 += Pr[3 * 8 + w];
                }
                float gi = s0 + x0;
                float gf = s1 + x1;
                float gg = s2 + x2;
                float go = s3 + x3;
                float i_ = 1.f / (1.f + __expf(-gi));
                float f_ = 1.f / (1.f + __expf(-gf));
                float gv = tanhf(gg);
                float o_ = 1.f / (1.f + __expf(-go));
                cst = f_ * cst + i_ * gv;
                float hv = o_ * tanhf(cst);
                g_Hall[(size_t)(t * B_ + b) * H_ + u0 + w] = __float2half(hv);
            }
            __syncthreads();
            if (tid == 0) {
                rel_add(&g_bar);
                unsigned tgt = (unsigned)(t + 1) * NBR;
                while (acq_ld(&g_bar) < tgt) { }
                if (cb == 0) rel_st(&g_step, (unsigned)(t + 1));
            }
            __syncthreads();
        }
        // fall through: join the GEMM2 tile queue
    }

    // ---------------- GEMM2 worker role ----------------
    for (;;) {
        if (tid == 0) s_tile = (int)atomicAdd(&g_tile, 1u);
        __syncthreads();
        int tile = s_tile;
        if (tile >= TILES) break;
        int mt = tile / NTN, nt = tile % NTN;

        if (tid == 0) {
            unsigned need = (unsigned)(4 * mt + 4);
            while (acq_ld(&g_step) < need) __nanosleep(256);
        }
        __syncthreads();

        gemm2_tile(smraw, mt * 128, nt * 128, b_out, out);
        __syncthreads();
    }
}

// ---------------- launch ----------------
extern "C" void kernel_launch(void* const* d_in, const int* in_sizes, int n_in,
                              void* d_out, int out_size)
{
    const float* enc   = (const float*)d_in[0];
    const int*   tgt32 = (const int*)d_in[1];
    const float* E     = (const float*)d_in[2];
    const float* W_ih  = (const float*)d_in[3];
    const float* W_hh  = (const float*)d_in[4];
    const float* b_ih  = (const float*)d_in[5];
    const float* b_hh  = (const float*)d_in[6];
    const float* b_out = (const float*)d_in[7];
    float* out = (float*)d_out;

    tok_kernel<<<M4_ / 256, 256>>>(tgt32);
    prep_kernel<<<4096, 256>>>(enc, E, W_ih, b_ih, b_hh);

    dim3 g0(G_ / 128, M4_ / 128);
    hgemm1_kernel<<<g0, 256>>>();

    cudaFuncSetAttribute(fused_kernel,
                         cudaFuncAttributeMaxDynamicSharedMemorySize, FUSED_SMEM);
    fused_kernel<<<288, 256, FUSED_SMEM>>>(W_hh, enc, b_out, out);
}